// round 13
// baseline (speedup 1.0000x reference)
#include <cuda_runtime.h>
#include <cuda_bf16.h>
#include <math.h>
#include <stdint.h>

// ---------------- problem constants ----------------
#define N3   405224   // 74^3 (divisible by 4)

typedef unsigned long long ull;

// ---------------- helpers ----------------
__device__ __forceinline__ ull pk(float lo, float hi) {
    ull r; asm("mov.b64 %0, {%1,%2};" : "=l"(r) : "f"(lo), "f"(hi)); return r;
}
__device__ __forceinline__ float2 unpk(ull p) {
    float2 f; asm("mov.b64 {%0,%1}, %2;" : "=f"(f.x), "=f"(f.y) : "l"(p)); return f;
}
__device__ __forceinline__ void fma2(ull& d, ull a, ull b, ull c) {
    asm("fma.rn.f32x2 %0, %1, %2, %3;" : "=l"(d) : "l"(a), "l"(b), "l"(c));
}
__device__ __forceinline__ uint32_t smem_u32(const void* p) {
    uint32_t a;
    asm("{ .reg .u64 t; cvta.to.shared.u64 t, %1; cvt.u32.u64 %0, t; }" : "=r"(a) : "l"(p));
    return a;
}
__device__ __forceinline__ void ldsm4(uint32_t& r0, uint32_t& r1, uint32_t& r2, uint32_t& r3,
                                      uint32_t addr) {
    asm volatile("ldmatrix.sync.aligned.m8n8.x4.shared.b16 {%0,%1,%2,%3}, [%4];"
                 : "=r"(r0), "=r"(r1), "=r"(r2), "=r"(r3) : "r"(addr));
}
__device__ __forceinline__ uint32_t packbf2(float x0, float x1) {
    __nv_bfloat16 h0 = __float2bfloat16(x0);
    __nv_bfloat16 h1 = __float2bfloat16(x1);
    return ((uint32_t)(*(uint16_t*)&h1) << 16) | (uint32_t)(*(uint16_t*)&h0);
}

// ---------------- device scratch ----------------
__device__ float g_buf1[2 * 32 * 78 * 78 * 78];   // conv1 out / conv3 out
__device__ float g_buf2[2 * 32 * 76 * 76 * 76];   // conv2 out
__device__ float g_kT[(size_t)2 * N3 * 64];       // j-major k
__device__ float g_v[2 * 64 * N3];                // d-major v
__device__ float g_slots[1024];
__device__ float g_q[1024];
__device__ float g_upd[1024];
__device__ float g_rowsum[16];
__device__ __nv_bfloat16 g_B2p[27 * 32 * 64];
__device__ __nv_bfloat16 g_B3p[27 * 32 * 64];

// =====================================================================
// Weight prep
// =====================================================================
__global__ void prepB_kernel(const float* __restrict__ w, __nv_bfloat16* __restrict__ Bg) {
    int idx = blockIdx.x * 256 + threadIdx.x;
    if (idx >= 27648) return;
    int t = idx >> 10;
    int r = idx & 1023;
    int n = r >> 5;
    int ci = r & 31;
    float x = w[(n * 32 + ci) * 27 + t];
    __nv_bfloat16 hi = __float2bfloat16(x);
    float rem = x - __bfloat162float(hi);
    __nv_bfloat16 lo = __float2bfloat16(rem);
    Bg[(t * 32 + n) * 64 + ci] = hi;
    Bg[(t * 32 + n) * 64 + 32 + ci] = lo;
}

// =====================================================================
// mma.sync bf16 split-2 implicit-GEMM conv3d (R12 version, unchanged).
// =====================================================================
#define BROW_W 36
#define BROW_B (BROW_W * 4)
#define B_BYTES (27 * 32 * BROW_B)
#define PROW_W 36
#define PROW_B (PROW_W * 4)
#define P_OFF  B_BYTES
#define P_BYTES (600 * PROW_B)
#define SMEM_MMA (P_OFF + P_BYTES)

#define MMA_BF16(d, a, b)                                                  \
    asm volatile("mma.sync.aligned.m16n8k16.row.col.f32.bf16.bf16.f32 "    \
                 "{%0,%1,%2,%3}, {%4,%5,%6,%7}, {%8,%9}, {%0,%1,%2,%3};"   \
                 : "+f"(d[0]), "+f"(d[1]), "+f"(d[2]), "+f"(d[3])          \
                 : "r"(a[0]), "r"(a[1]), "r"(a[2]), "r"(a[3]),             \
                   "r"(b[0]), "r"(b[1]))

__global__ __launch_bounds__(512)
void conv_mma_kernel(const float* __restrict__ in, const __nv_bfloat16* __restrict__ Bg,
                     const float* __restrict__ bias, float* __restrict__ out, int Di) {
    const int Do = Di - 2;
    extern __shared__ char smem[];
    __shared__ float s_bias[32];
    const int tid  = threadIdx.x;
    const int wid  = tid >> 5;
    const int lane = tid & 31;
    const int grp  = lane >> 2;
    const int tig  = lane & 3;

    {
        const uint32_t* src = (const uint32_t*)Bg;
        uint32_t* dst = (uint32_t*)smem;
        for (int i = tid; i < 27648; i += 512) {
            int row = i >> 5, w = i & 31;
            dst[row * BROW_W + w] = src[i];
        }
    }
    if (tid < 32) s_bias[tid] = bias[tid];
    __syncthreads();

    char* patch = smem + P_OFF;
    const uint32_t patch_u = smem_u32(patch);
    const uint32_t bsm_u   = smem_u32(smem);

    const int tokA = wid * 16 + (lane & 15);
    const int dA = tokA >> 6, hA = (tokA >> 3) & 7, wA = tokA & 7;
    const uint32_t aBase = patch_u + (uint32_t)(dA * 100 + hA * 10 + wA) * PROW_B + (lane >> 4) * 16;
    uint32_t bBase[2];
#pragma unroll
    for (int p = 0; p < 2; p++)
        bBase[p] = bsm_u + (uint32_t)(p * 16 + ((lane >> 4) << 3) + (lane & 7)) * BROW_B +
                   ((lane >> 3) & 1) * 16;

    const int tok0 = wid * 16 + grp;
    const int tok1 = tok0 + 8;

    int pd_[2], ph_[2], pw_[2], pofs_[2];
    bool sv_[2];
#pragma unroll
    for (int q = 0; q < 2; q++) {
        int s = tid + 512 * q;
        sv_[q] = (s < 600);
        int ss = sv_[q] ? s : 0;
        pd_[q] = ss / 100; int r2 = ss - pd_[q] * 100;
        ph_[q] = r2 / 10;  pw_[q] = r2 - ph_[q] * 10;
        pofs_[q] = ss * PROW_B;
    }

    const int nd = (Do + 3) >> 2, nhw = (Do + 7) >> 3;
    const int ntb = nd * nhw * nhw;
    const int DiDi = Di * Di;

    for (int ti = blockIdx.x; ti < 2 * ntb; ti += gridDim.x) {
        const int b = ti / ntb;
        int r = ti - b * ntb;
        const int td = r / (nhw * nhw); r -= td * (nhw * nhw);
        const int th = r / nhw, tw = r - (r / nhw) * nhw;
        const int d0 = td * 4, h0 = th * 8, w0 = tw * 8;

        __syncthreads();
#pragma unroll
        for (int q = 0; q < 2; q++) {
            if (!sv_[q]) continue;
            const int gd = d0 + pd_[q], gh = h0 + ph_[q], gw = w0 + pw_[q];
            const bool ok = (gd < Di) & (gh < Di) & (gw < Di);
            const float* src = in + (size_t)b * 32 * Di * DiDi + (size_t)(gd * Di + gh) * Di + gw;
            float xv[32];
#pragma unroll
            for (int ci = 0; ci < 32; ci++)
                xv[ci] = ok ? src[(size_t)ci * Di * DiDi] : 0.f;
            uint32_t* ph32 = (uint32_t*)(patch + pofs_[q]);
            uint32_t* pl32 = (uint32_t*)(patch + pofs_[q] + 64);
#pragma unroll
            for (int c2 = 0; c2 < 16; c2++) {
                float x0 = xv[2 * c2], x1 = xv[2 * c2 + 1];
                __nv_bfloat16 h0 = __float2bfloat16(x0);
                __nv_bfloat16 h1 = __float2bfloat16(x1);
                float r0 = x0 - __bfloat162float(h0);
                float r1 = x1 - __bfloat162float(h1);
                ph32[c2] = ((uint32_t)(*(uint16_t*)&h1) << 16) | (uint32_t)(*(uint16_t*)&h0);
                pl32[c2] = packbf2(r0, r1);
            }
        }
        __syncthreads();

        float acc[4][4];
#pragma unroll
        for (int nt = 0; nt < 4; nt++)
#pragma unroll
            for (int q = 0; q < 4; q++) acc[nt][q] = 0.f;

        uint32_t af[2][2][4];
        uint32_t bf[2][4][2][2];

#define LOAD_SLICE(BUF, SL)                                                       \
        do {                                                                      \
            const int t_ = (SL) >> 1, ks_ = (SL) & 1;                             \
            const int kd_ = t_ / 9, r9_ = t_ - kd_ * 9;                           \
            const int kh_ = r9_ / 3, kw_ = r9_ - kh_ * 3;                         \
            const uint32_t aAddr = aBase +                                        \
                (uint32_t)(kd_ * 100 + kh_ * 10 + kw_) * PROW_B + ks_ * 32;       \
            const uint32_t bOff = (uint32_t)t_ * 32 * BROW_B + ks_ * 32;          \
            ldsm4(af[BUF][0][0], af[BUF][0][1], af[BUF][0][2], af[BUF][0][3],     \
                  aAddr);                                                         \
            ldsm4(af[BUF][1][0], af[BUF][1][1], af[BUF][1][2], af[BUF][1][3],     \
                  aAddr + 64);                                                    \
            _Pragma("unroll")                                                     \
            for (int p_ = 0; p_ < 2; p_++) {                                      \
                _Pragma("unroll")                                                 \
                for (int sp_ = 0; sp_ < 2; sp_++) {                               \
                    uint32_t r0_, r1_, r2_, r3_;                                  \
                    ldsm4(r0_, r1_, r2_, r3_, bBase[p_] + bOff + sp_ * 64);       \
                    bf[BUF][2 * p_][sp_][0] = r0_;  bf[BUF][2 * p_][sp_][1] = r1_;\
                    bf[BUF][2 * p_ + 1][sp_][0] = r2_;                            \
                    bf[BUF][2 * p_ + 1][sp_][1] = r3_;                            \
                }                                                                 \
            }                                                                     \
        } while (0)

        LOAD_SLICE(0, 0);
#pragma unroll
        for (int sl = 0; sl < 54; sl++) {
            const int buf = sl & 1;
            if (sl < 53) {
                if (buf == 0) LOAD_SLICE(1, sl + 1);
                else          LOAD_SLICE(0, sl + 1);
            }
#pragma unroll
            for (int nt = 0; nt < 4; nt++)
                MMA_BF16(acc[nt], af[buf][0], bf[buf][nt][0]);
#pragma unroll
            for (int nt = 0; nt < 4; nt++)
                MMA_BF16(acc[nt], af[buf][1], bf[buf][nt][0]);
#pragma unroll
            for (int nt = 0; nt < 4; nt++)
                MMA_BF16(acc[nt], af[buf][0], bf[buf][nt][1]);
        }
#undef LOAD_SLICE

#pragma unroll
        for (int nt = 0; nt < 4; nt++)
#pragma unroll
            for (int q = 0; q < 4; q++) {
                int t = (q >> 1) ? tok1 : tok0;
                int c = nt * 8 + tig * 2 + (q & 1);
                int dd = t >> 6, hh = (t >> 3) & 7, ww = t & 7;
                int od = d0 + dd, oh = h0 + hh, ow = w0 + ww;
                if (od < Do && oh < Do && ow < Do) {
                    float v = acc[nt][q] + s_bias[c];
                    out[(((size_t)(b * 32 + c) * Do + od) * Do + oh) * Do + ow] =
                        v > 0.f ? v : 0.f;
                }
            }
    }
}

// =====================================================================
// Scalar conv for conv1 (CIN=4).
// =====================================================================
template <int CIN>
__global__ __launch_bounds__(256)
void conv3d_kernel(const float* __restrict__ in, const float* __restrict__ wg,
                   const float* __restrict__ bias, float* __restrict__ out,
                   int Di) {
    const int Do = Di - 2;
    const int tid = threadIdx.x;
    const int b  = blockIdx.z;
    const int nW = (Do + 7) >> 3;
    const int h0 = (blockIdx.x / nW) * 8;
    const int w0 = (blockIdx.x % nW) * 8;
    const int d0 = blockIdx.y * 4;

    extern __shared__ float smemf[];
    float* ws    = smemf;
    float* patch = smemf + CIN * 27 * 32;

    const int WTOT = 32 * CIN * 27;
    for (int idx = tid; idx < WTOT; idx += 256) {
        int co = idx / (CIN * 27);
        int r  = idx - co * (CIN * 27);
        ws[r * 32 + co] = wg[idx];
    }
    for (int idx = tid; idx < CIN * 600; idx += 256) {
        int ci = idx / 600;
        int r  = idx - ci * 600;
        int dd = r / 100;  int r2 = r - dd * 100;
        int hh = r2 / 10;  int ww = r2 - hh * 10;
        int gd = d0 + dd, gh = h0 + hh, gw = w0 + ww;
        float val = 0.f;
        if (gd < Di && gh < Di && gw < Di)
            val = in[(((b * CIN + ci) * Di + gd) * Di + gh) * Di + gw];
        patch[idx] = val;
    }
    __syncthreads();

    const int cout = tid >> 3;
    const int hg   = tid & 7;
    const float bv = bias[cout];

    float acc[4][8];
#pragma unroll
    for (int i = 0; i < 4; i++)
#pragma unroll
        for (int j = 0; j < 8; j++) acc[i][j] = 0.f;

    for (int ci = 0; ci < CIN; ci++) {
        float wr[27];
#pragma unroll
        for (int t = 0; t < 27; t++) wr[t] = ws[(ci * 27 + t) * 32 + cout];
        const float* pbase = patch + ci * 600;
#pragma unroll
        for (int kh = 0; kh < 3; kh++) {
            const float* rowb = pbase + (hg + kh) * 10;
#pragma unroll
            for (int dd = 0; dd < 6; dd++) {
                float row[10];
                const float2* rp = (const float2*)(rowb + dd * 100);
#pragma unroll
                for (int j = 0; j < 5; j++) ((float2*)row)[j] = rp[j];
#pragma unroll
                for (int kd = 0; kd < 3; kd++) {
                    const int dlo = dd - kd;
                    if (dlo >= 0 && dlo < 4) {
#pragma unroll
                        for (int kw = 0; kw < 3; kw++) {
                            float wv = wr[kd * 9 + kh * 3 + kw];
#pragma unroll
                            for (int w = 0; w < 8; w++)
                                acc[dlo][w] += wv * row[w + kw];
                        }
                    }
                }
            }
        }
    }
    __syncthreads();
#pragma unroll
    for (int dd = 0; dd < 4; dd++)
#pragma unroll
        for (int w = 0; w < 8; w++) {
            float v = acc[dd][w] + bv;
            patch[cout * 256 + dd * 64 + hg * 8 + w] = v > 0.f ? v : 0.f;
        }
    __syncthreads();
    const int DoDo = Do * Do;
    for (int idx = tid; idx < 8192; idx += 256) {
        int co = idx >> 8;
        int r  = idx & 255;
        int dd = r >> 6;
        int hh = (r >> 3) & 7;
        int w  = r & 7;
        int od = d0 + dd, oh = h0 + hh, ow = w0 + w;
        if (od < Do && oh < Do && ow < Do)
            out[((b * 32 + co) * Do + od) * DoDo + oh * Do + ow] = patch[idx];
    }
}

// =====================================================================
// feature LN + k/v projection. k -> j-major (g_kT), v -> d-major (g_v).
// =====================================================================
__global__ __launch_bounds__(256)
void lnkv_kernel(const float* __restrict__ x, const float* __restrict__ lg,
                 const float* __restrict__ lb, const float* __restrict__ kw,
                 const float* __restrict__ vw) {
    __shared__ float kws[2048], vws[2048], gs[32], bs[32];
    const int tid = threadIdx.x;
    for (int i = tid; i < 2048; i += 256) { kws[i] = kw[i]; vws[i] = vw[i]; }
    if (tid < 32) { gs[tid] = lg[tid]; bs[tid] = lb[tid]; }
    __syncthreads();
    const int b = blockIdx.y;
    const int j = blockIdx.x * 256 + tid;
    if (j >= N3) return;
    float xv[32];
    float s = 0.f;
#pragma unroll
    for (int c = 0; c < 32; c++) { xv[c] = x[(b * 32 + c) * N3 + j]; s += xv[c]; }
    const float m = s * (1.f / 32.f);
    float vs = 0.f;
#pragma unroll
    for (int c = 0; c < 32; c++) { float d = xv[c] - m; vs += d * d; }
    const float inv = rsqrtf(vs * (1.f / 32.f) + 1e-5f);
    ull xp[16];
#pragma unroll
    for (int c2 = 0; c2 < 16; c2++) {
        float a0 = (xv[2 * c2] - m) * inv * gs[2 * c2] + bs[2 * c2];
        float a1 = (xv[2 * c2 + 1] - m) * inv * gs[2 * c2 + 1] + bs[2 * c2 + 1];
        xp[c2] = pk(a0, a1);
    }
    float4* kout = (float4*)(g_kT + ((size_t)b * N3 + j) * 64);
#pragma unroll 2
    for (int dg = 0; dg < 16; dg++) {
        float kk[4];
#pragma unroll
        for (int e = 0; e < 4; e++) {
            int d = dg * 4 + e;
            const ull* k8 = (const ull*)(kws + d * 32);
            const ull* v8 = (const ull*)(vws + d * 32);
            ull ka = 0ull, va = 0ull;
#pragma unroll
            for (int c2 = 0; c2 < 16; c2++) {
                fma2(ka, xp[c2], k8[c2], ka);
                fma2(va, xp[c2], v8[c2], va);
            }
            float2 kp = unpk(ka), vp = unpk(va);
            kk[e] = kp.x + kp.y;
            g_v[(b * 64 + d) * N3 + j] = vp.x + vp.y;
        }
        kout[dg] = make_float4(kk[0], kk[1], kk[2], kk[3]);
    }
}

// =====================================================================
// q projection
// =====================================================================
__global__ __launch_bounds__(256)
void q_kernel(const float* __restrict__ slots, const float* __restrict__ lg,
              const float* __restrict__ lb, const float* __restrict__ qw) {
    __shared__ float s[1024], qws[4096], gs[64], bs[64], mm[16], iv[16];
    const int tid = threadIdx.x;
    for (int i = tid; i < 1024; i += 256) { s[i] = slots[i]; g_upd[i] = 0.f; }
    for (int i = tid; i < 4096; i += 256) qws[i] = qw[i];
    if (tid < 64) { gs[tid] = lg[tid]; bs[tid] = lb[tid]; }
    if (tid < 16) g_rowsum[tid] = 0.f;
    __syncthreads();
    if (tid < 16) {
        float sum = 0.f;
        for (int d = 0; d < 64; d++) sum += s[tid * 64 + d];
        float m = sum * (1.f / 64.f);
        float vs = 0.f;
        for (int d = 0; d < 64; d++) { float t = s[tid * 64 + d] - m; vs += t * t; }
        mm[tid] = m;
        iv[tid] = rsqrtf(vs * (1.f / 64.f) + 1e-5f);
    }
    __syncthreads();
    for (int k = 0; k < 4; k++) {
        int o = k * 256 + tid;
        int r = o >> 6, d = o & 63;
        float m = mm[r], inv = iv[r];
        float acc = 0.f;
#pragma unroll
        for (int c = 0; c < 64; c++)
            acc += ((s[r * 64 + c] - m) * inv * gs[c] + bs[c]) * qws[d * 64 + c];
        g_q[o] = acc * 0.125f;
    }
}

// =====================================================================
// fused attention: 43 KB smem (vs = 32x257 two-halves) -> 5 blocks/SM,
// grid.x = 444 so ~3.6 chunks per block. i=wid, d=lane(+32) mapping.
// =====================================================================
#define ATTN_SMEM ((512 + 2048 + 32 * 257) * 4)

__global__ __launch_bounds__(256)
void attn_kernel(float* __restrict__ attn_out) {
    extern __shared__ float sm[];
    float* qs = sm;             // 512
    float* as = sm + 512;       // 8*256
    float* vs = sm + 2560;      // 32*257
    const int tid  = threadIdx.x;
    const int b    = blockIdx.y;
    const int wid  = tid >> 5;
    const int lane = tid & 31;
    for (int i = tid; i < 512; i += 256) qs[i] = g_q[b * 512 + i];

    float acc0 = 0.f, acc1 = 0.f;
    float rsum[8];
#pragma unroll
    for (int i = 0; i < 8; i++) rsum[i] = 0.f;

    const int j4l = tid & 63;            // float4 column
    const int dbase = tid >> 6;          // 0..3

    const int nch = (N3 + 255) >> 8;
    for (int c = blockIdx.x; c < nch; c += gridDim.x) {
        const int j0 = c << 8;
        const int j  = j0 + tid;
        __syncthreads();
        // ---- dots + softmax ----
        float a[8];
        if (j < N3) {
            const float4* kp = (const float4*)(g_kT + ((size_t)b * N3 + j) * 64);
            float dots[8];
#pragma unroll
            for (int i = 0; i < 8; i++) dots[i] = 0.f;
#pragma unroll
            for (int dg = 0; dg < 16; dg++) {
                float4 kv = kp[dg];
#pragma unroll
                for (int i = 0; i < 8; i++) {
                    float4 q4 = *(const float4*)(qs + i * 64 + dg * 4);
                    dots[i] += q4.x * kv.x;
                    dots[i] += q4.y * kv.y;
                    dots[i] += q4.z * kv.z;
                    dots[i] += q4.w * kv.w;
                }
            }
            float mx = dots[0];
#pragma unroll
            for (int i = 1; i < 8; i++) mx = fmaxf(mx, dots[i]);
            float ssum = 0.f;
#pragma unroll
            for (int i = 0; i < 8; i++) { a[i] = __expf(dots[i] - mx); ssum += a[i]; }
            const float rinv = 1.f / ssum;
#pragma unroll
            for (int i = 0; i < 8; i++) a[i] = a[i] * rinv + 1e-8f;
            if (attn_out) {
#pragma unroll
                for (int i = 0; i < 8; i++)
                    attn_out[(b * 8 + i) * N3 + j] = a[i];
            }
        } else {
#pragma unroll
            for (int i = 0; i < 8; i++) a[i] = 0.f;
        }
#pragma unroll
        for (int i = 0; i < 8; i++) { as[i * 256 + tid] = a[i]; rsum[i] += a[i]; }

        // ---- v half 0 (d 0..31): 8 batched float4 LDG ----
        {
            const int jg4 = j0 + 4 * j4l;
            const bool vok = (jg4 < N3);
            float4 vbuf[8];
#pragma unroll
            for (int u = 0; u < 8; u++) {
                int d = dbase + u * 4;
                vbuf[u] = vok ? *(const float4*)(g_v + ((size_t)(b * 64 + d)) * N3 + jg4)
                              : make_float4(0.f, 0.f, 0.f, 0.f);
            }
#pragma unroll
            for (int u = 0; u < 8; u++) {
                int d = dbase + u * 4;
                float* dst = vs + d * 257 + 4 * j4l;
                dst[0] = vbuf[u].x; dst[1] = vbuf[u].y;
                dst[2] = vbuf[u].z; dst[3] = vbuf[u].w;
            }
        }
        __syncthreads();
        // phase2a: i=wid, d=lane
        {
            const float4* ap = (const float4*)(as + wid * 256);
            const float* vp = vs + lane * 257;
#pragma unroll 4
            for (int j4 = 0; j4 < 64; j4++) {
                float4 a4 = ap[j4];
                acc0 += a4.x * vp[4 * j4] + a4.y * vp[4 * j4 + 1] +
                        a4.z * vp[4 * j4 + 2] + a4.w * vp[4 * j4 + 3];
            }
        }
        __syncthreads();
        // ---- v half 1 (d 32..63) ----
        {
            const int jg4 = j0 + 4 * j4l;
            const bool vok = (jg4 < N3);
            float4 vbuf[8];
#pragma unroll
            for (int u = 0; u < 8; u++) {
                int d = 32 + dbase + u * 4;
                vbuf[u] = vok ? *(const float4*)(g_v + ((size_t)(b * 64 + d)) * N3 + jg4)
                              : make_float4(0.f, 0.f, 0.f, 0.f);
            }
#pragma unroll
            for (int u = 0; u < 8; u++) {
                int d = dbase + u * 4;
                float* dst = vs + d * 257 + 4 * j4l;
                dst[0] = vbuf[u].x; dst[1] = vbuf[u].y;
                dst[2] = vbuf[u].z; dst[3] = vbuf[u].w;
            }
        }
        __syncthreads();
        // phase2b: i=wid, d=32+lane
        {
            const float4* ap = (const float4*)(as + wid * 256);
            const float* vp = vs + lane * 257;
#pragma unroll 4
            for (int j4 = 0; j4 < 64; j4++) {
                float4 a4 = ap[j4];
                acc1 += a4.x * vp[4 * j4] + a4.y * vp[4 * j4 + 1] +
                        a4.z * vp[4 * j4 + 2] + a4.w * vp[4 * j4 + 3];
            }
        }
    }
    atomicAdd(&g_upd[(b * 8 + wid) * 64 + lane], acc0);
    atomicAdd(&g_upd[(b * 8 + wid) * 64 + 32 + lane], acc1);
#pragma unroll
    for (int i = 0; i < 8; i++) {
        float p = rsum[i];
#pragma unroll
        for (int off = 16; off; off >>= 1) p += __shfl_xor_sync(0xffffffffu, p, off);
        if (lane == 0) atomicAdd(&g_rowsum[b * 8 + i], p);
    }
}

// =====================================================================
// GRU cell + LN + MLP residual
// =====================================================================
__global__ __launch_bounds__(512)
void gru_kernel(const float* __restrict__ slots_prev,
                const float* __restrict__ wih, const float* __restrict__ whh,
                const float* __restrict__ bih, const float* __restrict__ bhh,
                const float* __restrict__ lng, const float* __restrict__ lnb,
                const float* __restrict__ w1, const float* __restrict__ rb1,
                const float* __restrict__ w2, const float* __restrict__ rb2,
                float* __restrict__ slots_final) {
    __shared__ float S[9216];
    float* u  = S;
    float* h  = S + 1024;
    float* xg = S + 2048;
    float* hg = S + 5120;
    float* nh = S + 8192;
    float* normed = S + 2048;
    float* t1     = S + 5120;
    const int tid = threadIdx.x;

    for (int k = 0; k < 2; k++) {
        int idx = k * 512 + tid;
        int r = idx >> 6;
        u[idx] = g_upd[idx] / g_rowsum[r];
        h[idx] = slots_prev[idx];
    }
    __syncthreads();
    for (int k = 0; k < 6; k++) {
        int p = k * 512 + tid;
        int r = p / 192, c = p - r * 192;
        float xa = bih[c], ha = bhh[c];
        const float* wr = wih + c * 64;
        const float* hr = whh + c * 64;
#pragma unroll 16
        for (int d = 0; d < 64; d++) {
            xa += u[r * 64 + d] * wr[d];
            ha += h[r * 64 + d] * hr[d];
        }
        xg[p] = xa; hg[p] = ha;
    }
    __syncthreads();
    for (int k = 0; k < 2; k++) {
        int idx = k * 512 + tid;
        int r = idx >> 6, d = idx & 63;
        float rg = 1.f / (1.f + expf(-(xg[r * 192 + d] + hg[r * 192 + d])));
        float z  = 1.f / (1.f + expf(-(xg[r * 192 + 64 + d] + hg[r * 192 + 64 + d])));
        float n  = tanhf(xg[r * 192 + 128 + d] + rg * hg[r * 192 + 128 + d]);
        nh[idx] = (1.f - z) * n + z * h[idx];
    }
    __syncthreads();
    {
        const int w = tid >> 5, lane = tid & 31;
        float e0 = nh[w * 64 + lane], e1 = nh[w * 64 + 32 + lane];
        float s = e0 + e1;
#pragma unroll
        for (int off = 16; off; off >>= 1) s += __shfl_xor_sync(0xffffffffu, s, off);
        float m = s * (1.f / 64.f);
        float d0 = e0 - m, d1 = e1 - m;
        float vq = d0 * d0 + d1 * d1;
#pragma unroll
        for (int off = 16; off; off >>= 1) vq += __shfl_xor_sync(0xffffffffu, vq, off);
        float inv = rsqrtf(vq * (1.f / 64.f) + 1e-5f);
        normed[w * 64 + lane]      = d0 * inv * lng[lane] + lnb[lane];
        normed[w * 64 + 32 + lane] = d1 * inv * lng[32 + lane] + lnb[32 + lane];
    }
    __syncthreads();
    for (int k = 0; k < 4; k++) {
        int p = k * 512 + tid;
        int r = p >> 7, c = p & 127;
        float acc = rb1[c];
        const float* wr = w1 + c * 64;
#pragma unroll 16
        for (int d = 0; d < 64; d++) acc += normed[r * 64 + d] * wr[d];
        t1[p] = fmaxf(acc, 0.f);
    }
    __syncthreads();
    for (int k = 0; k < 2; k++) {
        int idx = k * 512 + tid;
        int r = idx >> 6, d = idx & 63;
        float acc = rb2[d];
        const float* wr = w2 + d * 128;
#pragma unroll 16
        for (int c = 0; c < 128; c++) acc += t1[r * 128 + c] * wr[c];
        float val = nh[idx] + acc;
        g_slots[idx] = val;
        if (slots_final) slots_final[idx] = val;
    }
}

// =====================================================================
// host driver
// =====================================================================
extern "C" void kernel_launch(void* const* d_in, const int* in_sizes, int n_in,
                              void* d_out, int out_size) {
    (void)in_sizes; (void)n_in; (void)out_size;
    const float* p_slots = (const float*)d_in[0];
    const float* p_oin   = (const float*)d_in[1];
    const float* w1  = (const float*)d_in[2];
    const float* b1  = (const float*)d_in[3];
    const float* w2  = (const float*)d_in[4];
    const float* b2  = (const float*)d_in[5];
    const float* w3  = (const float*)d_in[6];
    const float* b3  = (const float*)d_in[7];
    const float* kw  = (const float*)d_in[8];
    const float* vw  = (const float*)d_in[9];
    const float* qlg = (const float*)d_in[10];
    const float* qlb = (const float*)d_in[11];
    const float* qw  = (const float*)d_in[12];
    const float* gwih = (const float*)d_in[13];
    const float* gwhh = (const float*)d_in[14];
    const float* gbih = (const float*)d_in[15];
    const float* gbhh = (const float*)d_in[16];
    const float* rlg = (const float*)d_in[17];
    const float* rlb = (const float*)d_in[18];
    const float* rw1 = (const float*)d_in[19];
    const float* rb1 = (const float*)d_in[20];
    const float* rw2 = (const float*)d_in[21];
    const float* rb2 = (const float*)d_in[22];
    const float* flg = (const float*)d_in[23];
    const float* flb = (const float*)d_in[24];
    float* out = (float*)d_out;

    const size_t smem4  = (size_t)(4 * 27 * 32 + 8192) * sizeof(float);
    cudaFuncSetAttribute(conv3d_kernel<4>, cudaFuncAttributeMaxDynamicSharedMemorySize, (int)smem4);
    cudaFuncSetAttribute(conv_mma_kernel, cudaFuncAttributeMaxDynamicSharedMemorySize, SMEM_MMA);
    cudaFuncSetAttribute(attn_kernel, cudaFuncAttributeMaxDynamicSharedMemorySize, ATTN_SMEM);

    float *buf1, *buf2, *slots_g;
    __nv_bfloat16 *B2p, *B3p;
    cudaGetSymbolAddress((void**)&buf1, g_buf1);
    cudaGetSymbolAddress((void**)&buf2, g_buf2);
    cudaGetSymbolAddress((void**)&slots_g, g_slots);
    cudaGetSymbolAddress((void**)&B2p, g_B2p);
    cudaGetSymbolAddress((void**)&B3p, g_B3p);

    prepB_kernel<<<108, 256>>>(w2, B2p);
    prepB_kernel<<<108, 256>>>(w3, B3p);

    // conv1: 80 -> 78 (scalar, CIN=4)
    conv3d_kernel<4><<<dim3(10 * 10, 20, 2), 256, smem4>>>(p_oin, w1, b1, buf1, 80);
    // conv2: 78 -> 76
    conv_mma_kernel<<<148, 512, SMEM_MMA>>>(buf1, B2p, b2, buf2, 78);
    // conv3: 76 -> 74
    conv_mma_kernel<<<148, 512, SMEM_MMA>>>(buf2, B3p, b3, buf1, 76);
    // feature LN + k/v projection (k j-major, v d-major)
    lnkv_kernel<<<dim3((N3 + 255) / 256, 2), 256>>>(buf1, flg, flb, kw, vw);

    for (int it = 0; it < 3; it++) {
        const float* sp = (it == 0) ? p_slots : slots_g;
        q_kernel<<<1, 256>>>(sp, qlg, qlb, qw);
        attn_kernel<<<dim3(444, 2), 256, ATTN_SMEM>>>((it == 2) ? (out + 1024) : (float*)0);
        gru_kernel<<<1, 512>>>(sp, gwih, gwhh, gbih, gbhh, rlg, rlb,
                               rw1, rb1, rw2, rb2, (it == 2) ? out : (float*)0);
    }
}

// round 14
// speedup vs baseline: 1.0407x; 1.0407x over previous
#include <cuda_runtime.h>
#include <cuda_bf16.h>
#include <math.h>
#include <stdint.h>

// ---------------- problem constants ----------------
#define N3   405224   // 74^3 (divisible by 4)

typedef unsigned long long ull;

// ---------------- helpers ----------------
__device__ __forceinline__ ull pk(float lo, float hi) {
    ull r; asm("mov.b64 %0, {%1,%2};" : "=l"(r) : "f"(lo), "f"(hi)); return r;
}
__device__ __forceinline__ float2 unpk(ull p) {
    float2 f; asm("mov.b64 {%0,%1}, %2;" : "=f"(f.x), "=f"(f.y) : "l"(p)); return f;
}
__device__ __forceinline__ void fma2(ull& d, ull a, ull b, ull c) {
    asm("fma.rn.f32x2 %0, %1, %2, %3;" : "=l"(d) : "l"(a), "l"(b), "l"(c));
}
__device__ __forceinline__ uint32_t smem_u32(const void* p) {
    uint32_t a;
    asm("{ .reg .u64 t; cvta.to.shared.u64 t, %1; cvt.u32.u64 %0, t; }" : "=r"(a) : "l"(p));
    return a;
}
__device__ __forceinline__ void ldsm4(uint32_t& r0, uint32_t& r1, uint32_t& r2, uint32_t& r3,
                                      uint32_t addr) {
    asm volatile("ldmatrix.sync.aligned.m8n8.x4.shared.b16 {%0,%1,%2,%3}, [%4];"
                 : "=r"(r0), "=r"(r1), "=r"(r2), "=r"(r3) : "r"(addr));
}
__device__ __forceinline__ uint32_t packbf2(float x0, float x1) {
    __nv_bfloat16 h0 = __float2bfloat16(x0);
    __nv_bfloat16 h1 = __float2bfloat16(x1);
    return ((uint32_t)(*(uint16_t*)&h1) << 16) | (uint32_t)(*(uint16_t*)&h0);
}

// ---------------- device scratch ----------------
__device__ float g_buf1[2 * 32 * 78 * 78 * 78];   // conv1 out / conv3 out
__device__ float g_buf2[2 * 32 * 76 * 76 * 76];   // conv2 out
__device__ float g_k[2 * 64 * N3];                // d-major k
__device__ float g_v[2 * 64 * N3];                // d-major v
__device__ float g_attn[2 * 8 * N3];              // attn probs scratch (iters 0,1)
__device__ float g_slots[1024];
__device__ float g_q[1024];
__device__ float g_upd[1024];
__device__ float g_rowsum[16];
__device__ __nv_bfloat16 g_B2p[27 * 32 * 64];
__device__ __nv_bfloat16 g_B3p[27 * 32 * 64];

// =====================================================================
// Weight prep
// =====================================================================
__global__ void prepB_kernel(const float* __restrict__ w, __nv_bfloat16* __restrict__ Bg) {
    int idx = blockIdx.x * 256 + threadIdx.x;
    if (idx >= 27648) return;
    int t = idx >> 10;
    int r = idx & 1023;
    int n = r >> 5;
    int ci = r & 31;
    float x = w[(n * 32 + ci) * 27 + t];
    __nv_bfloat16 hi = __float2bfloat16(x);
    float rem = x - __bfloat162float(hi);
    __nv_bfloat16 lo = __float2bfloat16(rem);
    Bg[(t * 32 + n) * 64 + ci] = hi;
    Bg[(t * 32 + n) * 64 + 32 + ci] = lo;
}

// =====================================================================
// mma.sync bf16 split-2 implicit-GEMM conv3d (R12 version, unchanged).
// =====================================================================
#define BROW_W 36
#define BROW_B (BROW_W * 4)
#define B_BYTES (27 * 32 * BROW_B)
#define PROW_W 36
#define PROW_B (PROW_W * 4)
#define P_OFF  B_BYTES
#define P_BYTES (600 * PROW_B)
#define SMEM_MMA (P_OFF + P_BYTES)

#define MMA_BF16(d, a, b)                                                  \
    asm volatile("mma.sync.aligned.m16n8k16.row.col.f32.bf16.bf16.f32 "    \
                 "{%0,%1,%2,%3}, {%4,%5,%6,%7}, {%8,%9}, {%0,%1,%2,%3};"   \
                 : "+f"(d[0]), "+f"(d[1]), "+f"(d[2]), "+f"(d[3])          \
                 : "r"(a[0]), "r"(a[1]), "r"(a[2]), "r"(a[3]),             \
                   "r"(b[0]), "r"(b[1]))

__global__ __launch_bounds__(512)
void conv_mma_kernel(const float* __restrict__ in, const __nv_bfloat16* __restrict__ Bg,
                     const float* __restrict__ bias, float* __restrict__ out, int Di) {
    const int Do = Di - 2;
    extern __shared__ char smem[];
    __shared__ float s_bias[32];
    const int tid  = threadIdx.x;
    const int wid  = tid >> 5;
    const int lane = tid & 31;
    const int grp  = lane >> 2;
    const int tig  = lane & 3;

    {
        const uint32_t* src = (const uint32_t*)Bg;
        uint32_t* dst = (uint32_t*)smem;
        for (int i = tid; i < 27648; i += 512) {
            int row = i >> 5, w = i & 31;
            dst[row * BROW_W + w] = src[i];
        }
    }
    if (tid < 32) s_bias[tid] = bias[tid];
    __syncthreads();

    char* patch = smem + P_OFF;
    const uint32_t patch_u = smem_u32(patch);
    const uint32_t bsm_u   = smem_u32(smem);

    const int tokA = wid * 16 + (lane & 15);
    const int dA = tokA >> 6, hA = (tokA >> 3) & 7, wA = tokA & 7;
    const uint32_t aBase = patch_u + (uint32_t)(dA * 100 + hA * 10 + wA) * PROW_B + (lane >> 4) * 16;
    uint32_t bBase[2];
#pragma unroll
    for (int p = 0; p < 2; p++)
        bBase[p] = bsm_u + (uint32_t)(p * 16 + ((lane >> 4) << 3) + (lane & 7)) * BROW_B +
                   ((lane >> 3) & 1) * 16;

    const int tok0 = wid * 16 + grp;
    const int tok1 = tok0 + 8;

    int pd_[2], ph_[2], pw_[2], pofs_[2];
    bool sv_[2];
#pragma unroll
    for (int q = 0; q < 2; q++) {
        int s = tid + 512 * q;
        sv_[q] = (s < 600);
        int ss = sv_[q] ? s : 0;
        pd_[q] = ss / 100; int r2 = ss - pd_[q] * 100;
        ph_[q] = r2 / 10;  pw_[q] = r2 - ph_[q] * 10;
        pofs_[q] = ss * PROW_B;
    }

    const int nd = (Do + 3) >> 2, nhw = (Do + 7) >> 3;
    const int ntb = nd * nhw * nhw;
    const int DiDi = Di * Di;

    for (int ti = blockIdx.x; ti < 2 * ntb; ti += gridDim.x) {
        const int b = ti / ntb;
        int r = ti - b * ntb;
        const int td = r / (nhw * nhw); r -= td * (nhw * nhw);
        const int th = r / nhw, tw = r - (r / nhw) * nhw;
        const int d0 = td * 4, h0 = th * 8, w0 = tw * 8;

        __syncthreads();
#pragma unroll
        for (int q = 0; q < 2; q++) {
            if (!sv_[q]) continue;
            const int gd = d0 + pd_[q], gh = h0 + ph_[q], gw = w0 + pw_[q];
            const bool ok = (gd < Di) & (gh < Di) & (gw < Di);
            const float* src = in + (size_t)b * 32 * Di * DiDi + (size_t)(gd * Di + gh) * Di + gw;
            float xv[32];
#pragma unroll
            for (int ci = 0; ci < 32; ci++)
                xv[ci] = ok ? src[(size_t)ci * Di * DiDi] : 0.f;
            uint32_t* ph32 = (uint32_t*)(patch + pofs_[q]);
            uint32_t* pl32 = (uint32_t*)(patch + pofs_[q] + 64);
#pragma unroll
            for (int c2 = 0; c2 < 16; c2++) {
                float x0 = xv[2 * c2], x1 = xv[2 * c2 + 1];
                __nv_bfloat16 h0 = __float2bfloat16(x0);
                __nv_bfloat16 h1 = __float2bfloat16(x1);
                float r0 = x0 - __bfloat162float(h0);
                float r1 = x1 - __bfloat162float(h1);
                ph32[c2] = ((uint32_t)(*(uint16_t*)&h1) << 16) | (uint32_t)(*(uint16_t*)&h0);
                pl32[c2] = packbf2(r0, r1);
            }
        }
        __syncthreads();

        float acc[4][4];
#pragma unroll
        for (int nt = 0; nt < 4; nt++)
#pragma unroll
            for (int q = 0; q < 4; q++) acc[nt][q] = 0.f;

        uint32_t af[2][2][4];
        uint32_t bf[2][4][2][2];

#define LOAD_SLICE(BUF, SL)                                                       \
        do {                                                                      \
            const int t_ = (SL) >> 1, ks_ = (SL) & 1;                             \
            const int kd_ = t_ / 9, r9_ = t_ - kd_ * 9;                           \
            const int kh_ = r9_ / 3, kw_ = r9_ - kh_ * 3;                         \
            const uint32_t aAddr = aBase +                                        \
                (uint32_t)(kd_ * 100 + kh_ * 10 + kw_) * PROW_B + ks_ * 32;       \
            const uint32_t bOff = (uint32_t)t_ * 32 * BROW_B + ks_ * 32;          \
            ldsm4(af[BUF][0][0], af[BUF][0][1], af[BUF][0][2], af[BUF][0][3],     \
                  aAddr);                                                         \
            ldsm4(af[BUF][1][0], af[BUF][1][1], af[BUF][1][2], af[BUF][1][3],     \
                  aAddr + 64);                                                    \
            _Pragma("unroll")                                                     \
            for (int p_ = 0; p_ < 2; p_++) {                                      \
                _Pragma("unroll")                                                 \
                for (int sp_ = 0; sp_ < 2; sp_++) {                               \
                    uint32_t r0_, r1_, r2_, r3_;                                  \
                    ldsm4(r0_, r1_, r2_, r3_, bBase[p_] + bOff + sp_ * 64);       \
                    bf[BUF][2 * p_][sp_][0] = r0_;  bf[BUF][2 * p_][sp_][1] = r1_;\
                    bf[BUF][2 * p_ + 1][sp_][0] = r2_;                            \
                    bf[BUF][2 * p_ + 1][sp_][1] = r3_;                            \
                }                                                                 \
            }                                                                     \
        } while (0)

        LOAD_SLICE(0, 0);
#pragma unroll
        for (int sl = 0; sl < 54; sl++) {
            const int buf = sl & 1;
            if (sl < 53) {
                if (buf == 0) LOAD_SLICE(1, sl + 1);
                else          LOAD_SLICE(0, sl + 1);
            }
#pragma unroll
            for (int nt = 0; nt < 4; nt++)
                MMA_BF16(acc[nt], af[buf][0], bf[buf][nt][0]);
#pragma unroll
            for (int nt = 0; nt < 4; nt++)
                MMA_BF16(acc[nt], af[buf][1], bf[buf][nt][0]);
#pragma unroll
            for (int nt = 0; nt < 4; nt++)
                MMA_BF16(acc[nt], af[buf][0], bf[buf][nt][1]);
        }
#undef LOAD_SLICE

#pragma unroll
        for (int nt = 0; nt < 4; nt++)
#pragma unroll
            for (int q = 0; q < 4; q++) {
                int t = (q >> 1) ? tok1 : tok0;
                int c = nt * 8 + tig * 2 + (q & 1);
                int dd = t >> 6, hh = (t >> 3) & 7, ww = t & 7;
                int od = d0 + dd, oh = h0 + hh, ow = w0 + ww;
                if (od < Do && oh < Do && ow < Do) {
                    float v = acc[nt][q] + s_bias[c];
                    out[(((size_t)(b * 32 + c) * Do + od) * Do + oh) * Do + ow] =
                        v > 0.f ? v : 0.f;
                }
            }
    }
}

// =====================================================================
// Scalar conv for conv1 (CIN=4).
// =====================================================================
template <int CIN>
__global__ __launch_bounds__(256)
void conv3d_kernel(const float* __restrict__ in, const float* __restrict__ wg,
                   const float* __restrict__ bias, float* __restrict__ out,
                   int Di) {
    const int Do = Di - 2;
    const int tid = threadIdx.x;
    const int b  = blockIdx.z;
    const int nW = (Do + 7) >> 3;
    const int h0 = (blockIdx.x / nW) * 8;
    const int w0 = (blockIdx.x % nW) * 8;
    const int d0 = blockIdx.y * 4;

    extern __shared__ float smemf[];
    float* ws    = smemf;
    float* patch = smemf + CIN * 27 * 32;

    const int WTOT = 32 * CIN * 27;
    for (int idx = tid; idx < WTOT; idx += 256) {
        int co = idx / (CIN * 27);
        int r  = idx - co * (CIN * 27);
        ws[r * 32 + co] = wg[idx];
    }
    for (int idx = tid; idx < CIN * 600; idx += 256) {
        int ci = idx / 600;
        int r  = idx - ci * 600;
        int dd = r / 100;  int r2 = r - dd * 100;
        int hh = r2 / 10;  int ww = r2 - hh * 10;
        int gd = d0 + dd, gh = h0 + hh, gw = w0 + ww;
        float val = 0.f;
        if (gd < Di && gh < Di && gw < Di)
            val = in[(((b * CIN + ci) * Di + gd) * Di + gh) * Di + gw];
        patch[idx] = val;
    }
    __syncthreads();

    const int cout = tid >> 3;
    const int hg   = tid & 7;
    const float bv = bias[cout];

    float acc[4][8];
#pragma unroll
    for (int i = 0; i < 4; i++)
#pragma unroll
        for (int j = 0; j < 8; j++) acc[i][j] = 0.f;

    for (int ci = 0; ci < CIN; ci++) {
        float wr[27];
#pragma unroll
        for (int t = 0; t < 27; t++) wr[t] = ws[(ci * 27 + t) * 32 + cout];
        const float* pbase = patch + ci * 600;
#pragma unroll
        for (int kh = 0; kh < 3; kh++) {
            const float* rowb = pbase + (hg + kh) * 10;
#pragma unroll
            for (int dd = 0; dd < 6; dd++) {
                float row[10];
                const float2* rp = (const float2*)(rowb + dd * 100);
#pragma unroll
                for (int j = 0; j < 5; j++) ((float2*)row)[j] = rp[j];
#pragma unroll
                for (int kd = 0; kd < 3; kd++) {
                    const int dlo = dd - kd;
                    if (dlo >= 0 && dlo < 4) {
#pragma unroll
                        for (int kw = 0; kw < 3; kw++) {
                            float wv = wr[kd * 9 + kh * 3 + kw];
#pragma unroll
                            for (int w = 0; w < 8; w++)
                                acc[dlo][w] += wv * row[w + kw];
                        }
                    }
                }
            }
        }
    }
    __syncthreads();
#pragma unroll
    for (int dd = 0; dd < 4; dd++)
#pragma unroll
        for (int w = 0; w < 8; w++) {
            float v = acc[dd][w] + bv;
            patch[cout * 256 + dd * 64 + hg * 8 + w] = v > 0.f ? v : 0.f;
        }
    __syncthreads();
    const int DoDo = Do * Do;
    for (int idx = tid; idx < 8192; idx += 256) {
        int co = idx >> 8;
        int r  = idx & 255;
        int dd = r >> 6;
        int hh = (r >> 3) & 7;
        int w  = r & 7;
        int od = d0 + dd, oh = h0 + hh, ow = w0 + w;
        if (od < Do && oh < Do && ow < Do)
            out[((b * 32 + co) * Do + od) * DoDo + oh * Do + ow] = patch[idx];
    }
}

// =====================================================================
// feature LN + k/v projection, both d-major.
// =====================================================================
__global__ __launch_bounds__(256)
void lnkv_kernel(const float* __restrict__ x, const float* __restrict__ lg,
                 const float* __restrict__ lb, const float* __restrict__ kw,
                 const float* __restrict__ vw) {
    __shared__ float kws[2048], vws[2048], gs[32], bs[32];
    const int tid = threadIdx.x;
    for (int i = tid; i < 2048; i += 256) { kws[i] = kw[i]; vws[i] = vw[i]; }
    if (tid < 32) { gs[tid] = lg[tid]; bs[tid] = lb[tid]; }
    __syncthreads();
    const int b = blockIdx.y;
    const int j = blockIdx.x * 256 + tid;
    if (j >= N3) return;
    float xv[32];
    float s = 0.f;
#pragma unroll
    for (int c = 0; c < 32; c++) { xv[c] = x[(b * 32 + c) * N3 + j]; s += xv[c]; }
    const float m = s * (1.f / 32.f);
    float vs = 0.f;
#pragma unroll
    for (int c = 0; c < 32; c++) { float d = xv[c] - m; vs += d * d; }
    const float inv = rsqrtf(vs * (1.f / 32.f) + 1e-5f);
    ull xp[16];
#pragma unroll
    for (int c2 = 0; c2 < 16; c2++) {
        float a0 = (xv[2 * c2] - m) * inv * gs[2 * c2] + bs[2 * c2];
        float a1 = (xv[2 * c2 + 1] - m) * inv * gs[2 * c2 + 1] + bs[2 * c2 + 1];
        xp[c2] = pk(a0, a1);
    }
#pragma unroll 4
    for (int d = 0; d < 64; d++) {
        const ull* k8 = (const ull*)(kws + d * 32);
        const ull* v8 = (const ull*)(vws + d * 32);
        ull ka = 0ull, va = 0ull;
#pragma unroll
        for (int c2 = 0; c2 < 16; c2++) {
            fma2(ka, xp[c2], k8[c2], ka);
            fma2(va, xp[c2], v8[c2], va);
        }
        float2 kp = unpk(ka), vp = unpk(va);
        g_k[(b * 64 + d) * N3 + j] = kp.x + kp.y;
        g_v[(b * 64 + d) * N3 + j] = vp.x + vp.y;
    }
}

// =====================================================================
// q projection
// =====================================================================
__global__ __launch_bounds__(256)
void q_kernel(const float* __restrict__ slots, const float* __restrict__ lg,
              const float* __restrict__ lb, const float* __restrict__ qw) {
    __shared__ float s[1024], qws[4096], gs[64], bs[64], mm[16], iv[16];
    const int tid = threadIdx.x;
    for (int i = tid; i < 1024; i += 256) { s[i] = slots[i]; g_upd[i] = 0.f; }
    for (int i = tid; i < 4096; i += 256) qws[i] = qw[i];
    if (tid < 64) { gs[tid] = lg[tid]; bs[tid] = lb[tid]; }
    if (tid < 16) g_rowsum[tid] = 0.f;
    __syncthreads();
    if (tid < 16) {
        float sum = 0.f;
        for (int d = 0; d < 64; d++) sum += s[tid * 64 + d];
        float m = sum * (1.f / 64.f);
        float vs = 0.f;
        for (int d = 0; d < 64; d++) { float t = s[tid * 64 + d] - m; vs += t * t; }
        mm[tid] = m;
        iv[tid] = rsqrtf(vs * (1.f / 64.f) + 1e-5f);
    }
    __syncthreads();
    for (int k = 0; k < 4; k++) {
        int o = k * 256 + tid;
        int r = o >> 6, d = o & 63;
        float m = mm[r], inv = iv[r];
        float acc = 0.f;
#pragma unroll
        for (int c = 0; c < 64; c++)
            acc += ((s[r * 64 + c] - m) * inv * gs[c] + bs[c]) * qws[d * 64 + c];
        g_q[o] = acc * 0.125f;
    }
}

// =====================================================================
// dots kernel: pure streaming, barrier-free after q load.
// thread = one token j. k d-major (warp-coalesced). Writes 8 probs.
// =====================================================================
__global__ __launch_bounds__(256)
void dots_kernel(float* __restrict__ aout) {
    __shared__ float qs[512];
    const int tid = threadIdx.x;
    const int b   = blockIdx.y;
    for (int i = tid; i < 512; i += 256) qs[i] = g_q[b * 512 + i];
    __syncthreads();
    const int j = blockIdx.x * 256 + tid;
    if (j >= N3) return;

    float dots[8];
#pragma unroll
    for (int i = 0; i < 8; i++) dots[i] = 0.f;
#pragma unroll
    for (int dgb = 0; dgb < 4; dgb++) {
        float kv[16];
#pragma unroll
        for (int u = 0; u < 16; u++)
            kv[u] = g_k[((size_t)(b * 64 + dgb * 16 + u)) * N3 + j];
#pragma unroll
        for (int u = 0; u < 16; u++) {
            float kd = kv[u];
#pragma unroll
            for (int i = 0; i < 8; i++)
                dots[i] += qs[i * 64 + dgb * 16 + u] * kd;
        }
    }
    float mx = dots[0];
#pragma unroll
    for (int i = 1; i < 8; i++) mx = fmaxf(mx, dots[i]);
    float ssum = 0.f;
    float a[8];
#pragma unroll
    for (int i = 0; i < 8; i++) { a[i] = __expf(dots[i] - mx); ssum += a[i]; }
    const float rinv = 1.f / ssum;
#pragma unroll
    for (int i = 0; i < 8; i++)
        aout[((size_t)(b * 8 + i)) * N3 + j] = a[i] * rinv + 1e-8f;
}

// =====================================================================
// update kernel: upd[i][d] = sum_j a[i][j]*v[j][d]; also rowsums.
// R12 phase-2 machinery; a read from global (written by dots_kernel).
// =====================================================================
#define UPD_SMEM ((2048 + 64 * 257) * 4)

__global__ __launch_bounds__(256)
void update_kernel(const float* __restrict__ ain) {
    extern __shared__ float sm[];
    float* as = sm;             // 8*256
    float* vs = sm + 2048;      // 64*257
    const int tid  = threadIdx.x;
    const int b    = blockIdx.y;
    const int dd   = tid & 63;
    const int ib   = tid >> 6;
    const int lane = tid & 31;

    float acc0 = 0.f, acc1 = 0.f;
    float rsum[8];
#pragma unroll
    for (int i = 0; i < 8; i++) rsum[i] = 0.f;

    const int j4l = tid & 63;
    const int dbase = tid >> 6;

    const int nch = (N3 + 255) >> 8;
    for (int c = blockIdx.x; c < nch; c += gridDim.x) {
        const int j0 = c << 8;
        __syncthreads();
        // a chunk: coalesced 8x256
        for (int idx = tid; idx < 2048; idx += 256) {
            int i = idx >> 8, jj = idx & 255;
            int jg = j0 + jj;
            as[i * 256 + jj] = (jg < N3) ? ain[((size_t)(b * 8 + i)) * N3 + jg] : 0.f;
        }
        // v chunk: 16 batched float4 LDG
        {
            const int jg4 = j0 + 4 * j4l;
            const bool vok = (jg4 < N3);
            float4 vbuf[16];
#pragma unroll
            for (int u = 0; u < 16; u++) {
                int d = dbase + u * 4;
                vbuf[u] = vok ? *(const float4*)(g_v + ((size_t)(b * 64 + d)) * N3 + jg4)
                              : make_float4(0.f, 0.f, 0.f, 0.f);
            }
#pragma unroll
            for (int u = 0; u < 16; u++) {
                int d = dbase + u * 4;
                float* dst = vs + d * 257 + 4 * j4l;
                dst[0] = vbuf[u].x; dst[1] = vbuf[u].y;
                dst[2] = vbuf[u].z; dst[3] = vbuf[u].w;
            }
        }
        __syncthreads();
#pragma unroll
        for (int i = 0; i < 8; i++) rsum[i] += as[i * 256 + tid];
        {
            const float4* ap0 = (const float4*)(as + ib * 256);
            const float4* ap1 = (const float4*)(as + (ib + 4) * 256);
            const float* vp  = vs + dd * 257;
#pragma unroll 4
            for (int j4 = 0; j4 < 64; j4++) {
                float4 a0 = ap0[j4], a1 = ap1[j4];
                float v0 = vp[4 * j4], v1 = vp[4 * j4 + 1],
                      v2 = vp[4 * j4 + 2], v3 = vp[4 * j4 + 3];
                acc0 += a0.x * v0 + a0.y * v1 + a0.z * v2 + a0.w * v3;
                acc1 += a1.x * v0 + a1.y * v1 + a1.z * v2 + a1.w * v3;
            }
        }
    }
    atomicAdd(&g_upd[(b * 8 + ib) * 64 + dd], acc0);
    atomicAdd(&g_upd[(b * 8 + ib + 4) * 64 + dd], acc1);
#pragma unroll
    for (int i = 0; i < 8; i++) {
        float p = rsum[i];
#pragma unroll
        for (int off = 16; off; off >>= 1) p += __shfl_xor_sync(0xffffffffu, p, off);
        if (lane == 0) atomicAdd(&g_rowsum[b * 8 + i], p);
    }
}

// =====================================================================
// GRU cell + LN + MLP residual
// =====================================================================
__global__ __launch_bounds__(512)
void gru_kernel(const float* __restrict__ slots_prev,
                const float* __restrict__ wih, const float* __restrict__ whh,
                const float* __restrict__ bih, const float* __restrict__ bhh,
                const float* __restrict__ lng, const float* __restrict__ lnb,
                const float* __restrict__ w1, const float* __restrict__ rb1,
                const float* __restrict__ w2, const float* __restrict__ rb2,
                float* __restrict__ slots_final) {
    __shared__ float S[9216];
    float* u  = S;
    float* h  = S + 1024;
    float* xg = S + 2048;
    float* hg = S + 5120;
    float* nh = S + 8192;
    float* normed = S + 2048;
    float* t1     = S + 5120;
    const int tid = threadIdx.x;

    for (int k = 0; k < 2; k++) {
        int idx = k * 512 + tid;
        int r = idx >> 6;
        u[idx] = g_upd[idx] / g_rowsum[r];
        h[idx] = slots_prev[idx];
    }
    __syncthreads();
    for (int k = 0; k < 6; k++) {
        int p = k * 512 + tid;
        int r = p / 192, c = p - r * 192;
        float xa = bih[c], ha = bhh[c];
        const float* wr = wih + c * 64;
        const float* hr = whh + c * 64;
#pragma unroll 16
        for (int d = 0; d < 64; d++) {
            xa += u[r * 64 + d] * wr[d];
            ha += h[r * 64 + d] * hr[d];
        }
        xg[p] = xa; hg[p] = ha;
    }
    __syncthreads();
    for (int k = 0; k < 2; k++) {
        int idx = k * 512 + tid;
        int r = idx >> 6, d = idx & 63;
        float rg = 1.f / (1.f + expf(-(xg[r * 192 + d] + hg[r * 192 + d])));
        float z  = 1.f / (1.f + expf(-(xg[r * 192 + 64 + d] + hg[r * 192 + 64 + d])));
        float n  = tanhf(xg[r * 192 + 128 + d] + rg * hg[r * 192 + 128 + d]);
        nh[idx] = (1.f - z) * n + z * h[idx];
    }
    __syncthreads();
    {
        const int w = tid >> 5, lane = tid & 31;
        float e0 = nh[w * 64 + lane], e1 = nh[w * 64 + 32 + lane];
        float s = e0 + e1;
#pragma unroll
        for (int off = 16; off; off >>= 1) s += __shfl_xor_sync(0xffffffffu, s, off);
        float m = s * (1.f / 64.f);
        float d0 = e0 - m, d1 = e1 - m;
        float vq = d0 * d0 + d1 * d1;
#pragma unroll
        for (int off = 16; off; off >>= 1) vq += __shfl_xor_sync(0xffffffffu, vq, off);
        float inv = rsqrtf(vq * (1.f / 64.f) + 1e-5f);
        normed[w * 64 + lane]      = d0 * inv * lng[lane] + lnb[lane];
        normed[w * 64 + 32 + lane] = d1 * inv * lng[32 + lane] + lnb[32 + lane];
    }
    __syncthreads();
    for (int k = 0; k < 4; k++) {
        int p = k * 512 + tid;
        int r = p >> 7, c = p & 127;
        float acc = rb1[c];
        const float* wr = w1 + c * 64;
#pragma unroll 16
        for (int d = 0; d < 64; d++) acc += normed[r * 64 + d] * wr[d];
        t1[p] = fmaxf(acc, 0.f);
    }
    __syncthreads();
    for (int k = 0; k < 2; k++) {
        int idx = k * 512 + tid;
        int r = idx >> 6, d = idx & 63;
        float acc = rb2[d];
        const float* wr = w2 + d * 128;
#pragma unroll 16
        for (int c = 0; c < 128; c++) acc += t1[r * 128 + c] * wr[c];
        float val = nh[idx] + acc;
        g_slots[idx] = val;
        if (slots_final) slots_final[idx] = val;
    }
}

// =====================================================================
// host driver
// =====================================================================
extern "C" void kernel_launch(void* const* d_in, const int* in_sizes, int n_in,
                              void* d_out, int out_size) {
    (void)in_sizes; (void)n_in; (void)out_size;
    const float* p_slots = (const float*)d_in[0];
    const float* p_oin   = (const float*)d_in[1];
    const float* w1  = (const float*)d_in[2];
    const float* b1  = (const float*)d_in[3];
    const float* w2  = (const float*)d_in[4];
    const float* b2  = (const float*)d_in[5];
    const float* w3  = (const float*)d_in[6];
    const float* b3  = (const float*)d_in[7];
    const float* kw  = (const float*)d_in[8];
    const float* vw  = (const float*)d_in[9];
    const float* qlg = (const float*)d_in[10];
    const float* qlb = (const float*)d_in[11];
    const float* qw  = (const float*)d_in[12];
    const float* gwih = (const float*)d_in[13];
    const float* gwhh = (const float*)d_in[14];
    const float* gbih = (const float*)d_in[15];
    const float* gbhh = (const float*)d_in[16];
    const float* rlg = (const float*)d_in[17];
    const float* rlb = (const float*)d_in[18];
    const float* rw1 = (const float*)d_in[19];
    const float* rb1 = (const float*)d_in[20];
    const float* rw2 = (const float*)d_in[21];
    const float* rb2 = (const float*)d_in[22];
    const float* flg = (const float*)d_in[23];
    const float* flb = (const float*)d_in[24];
    float* out = (float*)d_out;

    const size_t smem4  = (size_t)(4 * 27 * 32 + 8192) * sizeof(float);
    cudaFuncSetAttribute(conv3d_kernel<4>, cudaFuncAttributeMaxDynamicSharedMemorySize, (int)smem4);
    cudaFuncSetAttribute(conv_mma_kernel, cudaFuncAttributeMaxDynamicSharedMemorySize, SMEM_MMA);
    cudaFuncSetAttribute(update_kernel, cudaFuncAttributeMaxDynamicSharedMemorySize, UPD_SMEM);

    float *buf1, *buf2, *slots_g, *attn_g;
    __nv_bfloat16 *B2p, *B3p;
    cudaGetSymbolAddress((void**)&buf1, g_buf1);
    cudaGetSymbolAddress((void**)&buf2, g_buf2);
    cudaGetSymbolAddress((void**)&slots_g, g_slots);
    cudaGetSymbolAddress((void**)&attn_g, g_attn);
    cudaGetSymbolAddress((void**)&B2p, g_B2p);
    cudaGetSymbolAddress((void**)&B3p, g_B3p);

    prepB_kernel<<<108, 256>>>(w2, B2p);
    prepB_kernel<<<108, 256>>>(w3, B3p);

    // conv1: 80 -> 78 (scalar, CIN=4)
    conv3d_kernel<4><<<dim3(10 * 10, 20, 2), 256, smem4>>>(p_oin, w1, b1, buf1, 80);
    // conv2: 78 -> 76
    conv_mma_kernel<<<148, 512, SMEM_MMA>>>(buf1, B2p, b2, buf2, 78);
    // conv3: 76 -> 74
    conv_mma_kernel<<<148, 512, SMEM_MMA>>>(buf2, B3p, b3, buf1, 76);
    // feature LN + k/v projection (both d-major)
    lnkv_kernel<<<dim3((N3 + 255) / 256, 2), 256>>>(buf1, flg, flb, kw, vw);

    const int nblk = (N3 + 255) / 256;   // 1584
    for (int it = 0; it < 3; it++) {
        const float* sp = (it == 0) ? p_slots : slots_g;
        float* aptr = (it == 2) ? (out + 1024) : attn_g;
        q_kernel<<<1, 256>>>(sp, qlg, qlb, qw);
        dots_kernel<<<dim3(nblk, 2), 256>>>(aptr);
        update_kernel<<<dim3(296, 2), 256, UPD_SMEM>>>(aptr);
        gru_kernel<<<1, 512>>>(sp, gwih, gwhh, gbih, gbhh, rlg, rlb,
                               rw1, rb1, rw2, rb2, (it == 2) ? out : (float*)0);
    }
}